// round 15
// baseline (speedup 1.0000x reference)
#include <cuda_runtime.h>
#include <cuda_bf16.h>
#include <cuda_fp16.h>
#include <cstdint>

#define D 256
#define MAXM 100096   // >= N, multiple of 128
#define MAXE 1700000
#define SCANB 1024
#define MAXSB 128

// ---------------- scratch (device globals; no allocations) ----------------
__device__ __half g_t[(size_t)MAXM * D];   // aggregated features (fp16, GEMM-a input)
__device__ float g_u[(size_t)MAXM * D];    // GEMM-a output (fp32)
__device__ __half g_xh[(size_t)MAXM * D];  // fp16 copy of x (gather source)
__device__ __half g_hh[(size_t)MAXM * D];  // conv1 output h (fp16, gather source)
__device__ float g_sum[D];
__device__ float g_sumsq[D];
__device__ float g_scale[D];
__device__ float g_shift[D];
// weights pre-converted to fp16 hi/lo (w = wh + wl to ~2^-22): 4 matrices 256x256
__device__ __half g_wh[4][D * D];
__device__ __half g_wl[4][D * D];
// CSR scratch
__device__ int g_deg[MAXM];
__device__ int g_cursor[MAXM];
__device__ int g_rowptr[MAXM + 1];
__device__ int g_col[MAXE];
__device__ int g_bsum[MAXSB];

// ---------------- BN helpers ----------------
__global__ void zero_stats_kernel() {
    g_sum[threadIdx.x] = 0.f;
    g_sumsq[threadIdx.x] = 0.f;
}

// fp32 input stats (+ optional fused fp16 copy)
template <int WRITE_H>
__global__ void stats_kernel(const float* __restrict__ X, __half* __restrict__ XH,
                             int M) {
    int c = threadIdx.x;
    int rows = (M + gridDim.x - 1) / gridDim.x;
    int r0 = blockIdx.x * rows;
    int r1 = r0 + rows;
    if (r1 > M) r1 = M;
    float s = 0.f, q = 0.f;
    int r = r0;
    for (; r + 4 <= r1; r += 4) {
        float v0 = X[(size_t)(r + 0) * D + c];
        float v1 = X[(size_t)(r + 1) * D + c];
        float v2 = X[(size_t)(r + 2) * D + c];
        float v3 = X[(size_t)(r + 3) * D + c];
        s += (v0 + v1) + (v2 + v3);
        q += (v0 * v0 + v1 * v1) + (v2 * v2 + v3 * v3);
        if (WRITE_H) {
            XH[(size_t)(r + 0) * D + c] = __float2half_rn(v0);
            XH[(size_t)(r + 1) * D + c] = __float2half_rn(v1);
            XH[(size_t)(r + 2) * D + c] = __float2half_rn(v2);
            XH[(size_t)(r + 3) * D + c] = __float2half_rn(v3);
        }
    }
    for (; r < r1; r++) {
        float v = X[(size_t)r * D + c];
        s += v;
        q += v * v;
        if (WRITE_H) XH[(size_t)r * D + c] = __float2half_rn(v);
    }
    if (r1 > r0) {
        atomicAdd(&g_sum[c], s);
        atomicAdd(&g_sumsq[c], q);
    }
}

__global__ void finalize_stats_kernel(const float* __restrict__ gamma,
                                      const float* __restrict__ beta, int M) {
    int c = threadIdx.x;
    float invM = 1.f / (float)M;
    float mu = g_sum[c] * invM;
    float var = g_sumsq[c] * invM - mu * mu;
    float sc = gamma[c] * rsqrtf(var + 1e-5f);
    g_scale[c] = sc;
    g_shift[c] = beta[c] - mu * sc;
}

// ---------------- weight pre-conversion (fp16 hi/lo split), all 4 in one ----
__global__ void convert_w_kernel(const float* __restrict__ W0,
                                 const float* __restrict__ W1,
                                 const float* __restrict__ W2,
                                 const float* __restrict__ W3) {
    const float* Ws[4] = {W0, W1, W2, W3};
    int w = blockIdx.y;
    int i = blockIdx.x * blockDim.x + threadIdx.x;  // over D*D/2 pairs
    float2 v = ((const float2*)Ws[w])[i];
    __half2 hh = __floats2half2_rn(v.x, v.y);
    float2 f = __half22float2(hh);
    __half2 ll = __floats2half2_rn(v.x - f.x, v.y - f.y);
    ((__half2*)g_wh[w])[i] = hh;
    ((__half2*)g_wl[w])[i] = ll;
}

// ---------------- CSR build ----------------
__global__ void zero_deg_kernel(int M) {
    int i = blockIdx.x * blockDim.x + threadIdx.x;
    if (i < M) {
        g_deg[i] = 0;
        g_cursor[i] = 0;
    }
}

__global__ void hist_kernel(const int* __restrict__ dstIdx, int E) {
    int e = blockIdx.x * blockDim.x + threadIdx.x;
    if (e < E) atomicAdd(&g_deg[dstIdx[e]], 1);
}

__global__ void scan_block_kernel(int M) {
    __shared__ int sh[SCANB];
    int i = blockIdx.x * SCANB + threadIdx.x;
    int v = (i < M) ? g_deg[i] : 0;
    sh[threadIdx.x] = v;
    __syncthreads();
    for (int off = 1; off < SCANB; off <<= 1) {
        int t = (threadIdx.x >= off) ? sh[threadIdx.x - off] : 0;
        __syncthreads();
        sh[threadIdx.x] += t;
        __syncthreads();
    }
    if (i < M) g_rowptr[i] = sh[threadIdx.x] - v;
    if (threadIdx.x == SCANB - 1) g_bsum[blockIdx.x] = sh[SCANB - 1];
}

__global__ void scan_bsum_kernel(int nb) {
    if (threadIdx.x == 0) {
        int run = 0;
        for (int i = 0; i < nb; i++) {
            int v = g_bsum[i];
            g_bsum[i] = run;
            run += v;
        }
    }
}

__global__ void scan_add_kernel(int M, int E) {
    int i = blockIdx.x * SCANB + threadIdx.x;
    if (i < M) g_rowptr[i] += g_bsum[blockIdx.x];
    if (i == 0) g_rowptr[M] = E;
}

__global__ void fill_kernel(const int* __restrict__ srcIdx,
                            const int* __restrict__ dstIdx, int E) {
    int e = blockIdx.x * blockDim.x + threadIdx.x;
    if (e >= E) return;
    int d = dstIdx[e];
    int pos = g_rowptr[d] + atomicAdd(&g_cursor[d], 1);
    g_col[pos] = srcIdx[e];
}

// ---------------- CSR aggregation (fp16 src, fp16 out, MLP=4) ----------------
template <int BN_FOLD>
__global__ void agg_csr_half_kernel(const __half* __restrict__ feat,
                                    __half* __restrict__ out, int M) {
    int node = blockIdx.x * 8 + (threadIdx.x >> 5);
    if (node >= M) return;
    int lane = threadIdx.x & 31;
    int e0 = __ldg(&g_rowptr[node]);
    int e1 = __ldg(&g_rowptr[node + 1]);
    const uint4* base = (const uint4*)feat;

    float acc[8];
    {
        uint4 v = base[(size_t)node * 32 + lane];
        const __half2* h2 = (const __half2*)&v;
#pragma unroll
        for (int p = 0; p < 4; p++) {
            float2 f = __half22float2(h2[p]);
            acc[p * 2] = f.x;
            acc[p * 2 + 1] = f.y;
        }
    }
    int e = e0;
    for (; e + 4 <= e1; e += 4) {
        int s0 = __ldg(&g_col[e + 0]);
        int s1 = __ldg(&g_col[e + 1]);
        int s2 = __ldg(&g_col[e + 2]);
        int s3 = __ldg(&g_col[e + 3]);
        uint4 v0 = base[(size_t)s0 * 32 + lane];
        uint4 v1 = base[(size_t)s1 * 32 + lane];
        uint4 v2 = base[(size_t)s2 * 32 + lane];
        uint4 v3 = base[(size_t)s3 * 32 + lane];
        const __half2* a2 = (const __half2*)&v0;
        const __half2* b2 = (const __half2*)&v1;
        const __half2* c2 = (const __half2*)&v2;
        const __half2* d2 = (const __half2*)&v3;
#pragma unroll
        for (int p = 0; p < 4; p++) {
            float2 fa = __half22float2(a2[p]);
            float2 fb = __half22float2(b2[p]);
            float2 fc = __half22float2(c2[p]);
            float2 fd = __half22float2(d2[p]);
            acc[p * 2] += (fa.x + fb.x) + (fc.x + fd.x);
            acc[p * 2 + 1] += (fa.y + fb.y) + (fc.y + fd.y);
        }
    }
    for (; e < e1; e++) {
        int s = __ldg(&g_col[e]);
        uint4 v = base[(size_t)s * 32 + lane];
        const __half2* h2 = (const __half2*)&v;
#pragma unroll
        for (int p = 0; p < 4; p++) {
            float2 f = __half22float2(h2[p]);
            acc[p * 2] += f.x;
            acc[p * 2 + 1] += f.y;
        }
    }
    if (BN_FOLD) {
        float k = (float)(1 + (e1 - e0));
#pragma unroll
        for (int p = 0; p < 8; p++) {
            int c = lane * 8 + p;
            acc[p] = acc[p] * g_scale[c] + k * g_shift[c];
        }
    }
    uint4 o;
    __half2* o2 = (__half2*)&o;
#pragma unroll
    for (int p = 0; p < 4; p++)
        o2[p] = __floats2half2_rn(acc[p * 2], acc[p * 2 + 1]);
    ((uint4*)out)[(size_t)node * 32 + lane] = o;
}

// ---------------- common GEMM geometry ----------------
#define BK 32
#define AS 40    // As row stride (b16 elements)
#define BS 136   // Bs row stride (b16 elements)
#define NKT (D / BK)   // 8

#define MMA_F16(d, a, b)                                                          \
    asm volatile(                                                                 \
        "mma.sync.aligned.m16n8k16.row.col.f32.f16.f16.f32 "                      \
        "{%0,%1,%2,%3}, {%4,%5,%6,%7}, {%8,%9}, {%0,%1,%2,%3};"                   \
        : "+f"((d)[0]), "+f"((d)[1]), "+f"((d)[2]), "+f"((d)[3])                  \
        : "r"((a)[0]), "r"((a)[1]), "r"((a)[2]), "r"((a)[3]),                     \
          "r"((b)[0]), "r"((b)[1]))

// ---------------- GEMM-A: A fp16 exact, 2-term (a*wh + a*wl), fp32 out ------
__global__ __launch_bounds__(512, 1) void gemm_a_kernel(
    const __half* __restrict__ A, const __half* __restrict__ Wh,
    const __half* __restrict__ Wl, const float* __restrict__ bias,
    float* __restrict__ C, int M) {
    __shared__ __half As[128 * AS];
    __shared__ __half Bs_h[BK * BS];
    __shared__ __half Bs_l[BK * BS];

    int bm = blockIdx.x * 128;
    int bn = blockIdx.y * 128;
    int tid = threadIdx.x;
    int lane = tid & 31;
    int wid = tid >> 5;
    int warp_m = wid >> 2;   // 0..3
    int warp_n = wid & 3;    // 0..3

    float acc[2][4][4];
#pragma unroll
    for (int i = 0; i < 2; i++)
#pragma unroll
        for (int j = 0; j < 4; j++)
#pragma unroll
            for (int r = 0; r < 4; r++) acc[i][j][r] = 0.f;

    int a_row = tid >> 2;
    int a_kh = (tid & 3) * 8;
    bool a_valid = (bm + a_row) < M;
    int b_row = tid >> 4;
    int b_c8 = (tid & 15) * 8;

    uint32_t as_base = (uint32_t)__cvta_generic_to_shared(As);
    uint32_t bs_h_base = (uint32_t)__cvta_generic_to_shared(Bs_h);
    uint32_t bs_l_base = (uint32_t)__cvta_generic_to_shared(Bs_l);

    uint4 a_pf, bh_pf, bl_pf;
    auto load_g = [&](int k0) {
        a_pf = a_valid ? *(const uint4*)(A + (size_t)(bm + a_row) * D + k0 + a_kh)
                       : make_uint4(0u, 0u, 0u, 0u);
        size_t goff = (size_t)(k0 + b_row) * D + bn + b_c8;
        bh_pf = *(const uint4*)(Wh + goff);
        bl_pf = *(const uint4*)(Wl + goff);
    };

    load_g(0);
    for (int kt = 0; kt < NKT; kt++) {
        *(uint4*)&As[a_row * AS + a_kh] = a_pf;
        *(uint4*)&Bs_h[b_row * BS + b_c8] = bh_pf;
        *(uint4*)&Bs_l[b_row * BS + b_c8] = bl_pf;
        __syncthreads();
        if (kt + 1 < NKT) load_g((kt + 1) * BK);

#pragma unroll
        for (int k16 = 0; k16 < BK; k16 += 16) {
            uint32_t ah[2][4];
            uint32_t bh[4][2];
            uint32_t bl[4][2];
#pragma unroll
            for (int mi = 0; mi < 2; mi++) {
                int row = warp_m * 32 + mi * 16 + (lane & 15);
                int col = k16 + ((lane >> 4) << 3);
                uint32_t ad = as_base + (uint32_t)(row * AS + col) * 2;
                asm volatile("ldmatrix.sync.aligned.m8n8.x4.shared.b16 {%0,%1,%2,%3}, [%4];"
                             : "=r"(ah[mi][0]), "=r"(ah[mi][1]), "=r"(ah[mi][2]), "=r"(ah[mi][3])
                             : "r"(ad));
            }
#pragma unroll
            for (int ni = 0; ni < 4; ni++) {
                int row = k16 + (lane & 15);
                int col = warp_n * 32 + ni * 8;
                uint32_t bd = bs_h_base + (uint32_t)(row * BS + col) * 2;
                asm volatile("ldmatrix.sync.aligned.m8n8.x2.trans.shared.b16 {%0,%1}, [%2];"
                             : "=r"(bh[ni][0]), "=r"(bh[ni][1]) : "r"(bd));
                uint32_t bd2 = bs_l_base + (uint32_t)(row * BS + col) * 2;
                asm volatile("ldmatrix.sync.aligned.m8n8.x2.trans.shared.b16 {%0,%1}, [%2];"
                             : "=r"(bl[ni][0]), "=r"(bl[ni][1]) : "r"(bd2));
            }
#pragma unroll
            for (int mi = 0; mi < 2; mi++) {
#pragma unroll
                for (int ni = 0; ni < 4; ni++) {
                    MMA_F16(acc[mi][ni], ah[mi], bh[ni]);
                    MMA_F16(acc[mi][ni], ah[mi], bl[ni]);
                }
            }
        }
        __syncthreads();
    }

    // epilogue: bias + fp32 store (no relu: feeds BN stats)
#pragma unroll
    for (int mi = 0; mi < 2; mi++) {
#pragma unroll
        for (int ni = 0; ni < 4; ni++) {
            int r0 = bm + warp_m * 32 + mi * 16 + (lane >> 2);
            int c0 = bn + warp_n * 32 + ni * 8 + (lane & 3) * 2;
            float b0 = bias[c0], b1 = bias[c0 + 1];
            float* d = acc[mi][ni];
            if (r0 < M)
                *(float2*)&C[(size_t)r0 * D + c0] = make_float2(d[0] + b0, d[1] + b1);
            if (r0 + 8 < M)
                *(float2*)&C[(size_t)(r0 + 8) * D + c0] = make_float2(d[2] + b0, d[3] + b1);
        }
    }
}

// ---------------- GEMM-B: A fp32 + BN/relu, exact fp16 split, 3-term --------
template <int OUT_HALF>
__global__ __launch_bounds__(512, 1) void gemm_b_kernel(
    const float* __restrict__ A, const __half* __restrict__ Wh,
    const __half* __restrict__ Wl, const float* __restrict__ bias,
    void* __restrict__ Cv, int M) {
    __shared__ __half As_h[128 * AS];
    __shared__ __half As_l[128 * AS];
    __shared__ __half Bs_h[BK * BS];
    __shared__ __half Bs_l[BK * BS];

    int bm = blockIdx.x * 128;
    int bn = blockIdx.y * 128;
    int tid = threadIdx.x;
    int lane = tid & 31;
    int wid = tid >> 5;
    int warp_m = wid >> 2;
    int warp_n = wid & 3;

    float acc[2][4][4];
#pragma unroll
    for (int i = 0; i < 2; i++)
#pragma unroll
        for (int j = 0; j < 4; j++)
#pragma unroll
            for (int r = 0; r < 4; r++) acc[i][j][r] = 0.f;

    int a_row = tid >> 2;
    int a_kh = (tid & 3) * 8;
    bool a_valid = (bm + a_row) < M;
    int b_row = tid >> 4;
    int b_c8 = (tid & 15) * 8;

    uint32_t as_h_base = (uint32_t)__cvta_generic_to_shared(As_h);
    uint32_t as_l_base = (uint32_t)__cvta_generic_to_shared(As_l);
    uint32_t bs_h_base = (uint32_t)__cvta_generic_to_shared(Bs_h);
    uint32_t bs_l_base = (uint32_t)__cvta_generic_to_shared(Bs_l);

    float4 a_pf0, a_pf1;
    uint4 bh_pf, bl_pf;
    auto load_g = [&](int k0) {
        if (a_valid) {
            const float* Ar = A + (size_t)(bm + a_row) * D + k0 + a_kh;
            a_pf0 = *(const float4*)Ar;
            a_pf1 = *(const float4*)(Ar + 4);
        } else {
            a_pf0 = make_float4(0.f, 0.f, 0.f, 0.f);
            a_pf1 = a_pf0;
        }
        size_t goff = (size_t)(k0 + b_row) * D + bn + b_c8;
        bh_pf = *(const uint4*)(Wh + goff);
        bl_pf = *(const uint4*)(Wl + goff);
    };

    load_g(0);
    for (int kt = 0; kt < NKT; kt++) {
        int k0 = kt * BK;
        {
            float f[8] = {a_pf0.x, a_pf0.y, a_pf0.z, a_pf0.w,
                          a_pf1.x, a_pf1.y, a_pf1.z, a_pf1.w};
#pragma unroll
            for (int p = 0; p < 2; p++) {
                float4 s = ((const float4*)g_scale)[((k0 + a_kh) >> 2) + p];
                float4 sh = ((const float4*)g_shift)[((k0 + a_kh) >> 2) + p];
                f[p * 4 + 0] = fmaxf(f[p * 4 + 0] * s.x + sh.x, 0.f);
                f[p * 4 + 1] = fmaxf(f[p * 4 + 1] * s.y + sh.y, 0.f);
                f[p * 4 + 2] = fmaxf(f[p * 4 + 2] * s.z + sh.z, 0.f);
                f[p * 4 + 3] = fmaxf(f[p * 4 + 3] * s.w + sh.w, 0.f);
            }
            int off = a_row * AS + a_kh;
#pragma unroll
            for (int p = 0; p < 4; p++) {
                __half2 h2 = __floats2half2_rn(f[p * 2], f[p * 2 + 1]);
                float2 fb = __half22float2(h2);
                __half2 l2 = __floats2half2_rn(f[p * 2] - fb.x, f[p * 2 + 1] - fb.y);
                *(__half2*)&As_h[off + p * 2] = h2;
                *(__half2*)&As_l[off + p * 2] = l2;
            }
            *(uint4*)&Bs_h[b_row * BS + b_c8] = bh_pf;
            *(uint4*)&Bs_l[b_row * BS + b_c8] = bl_pf;
        }
        __syncthreads();
        if (kt + 1 < NKT) load_g(k0 + BK);

#pragma unroll
        for (int k16 = 0; k16 < BK; k16 += 16) {
            uint32_t ah[2][4];
            uint32_t al[2][4];
            uint32_t bh[4][2];
            uint32_t bl[4][2];
#pragma unroll
            for (int mi = 0; mi < 2; mi++) {
                int row = warp_m * 32 + mi * 16 + (lane & 15);
                int col = k16 + ((lane >> 4) << 3);
                uint32_t ad = as_h_base + (uint32_t)(row * AS + col) * 2;
                asm volatile("ldmatrix.sync.aligned.m8n8.x4.shared.b16 {%0,%1,%2,%3}, [%4];"
                             : "=r"(ah[mi][0]), "=r"(ah[mi][1]), "=r"(ah[mi][2]), "=r"(ah[mi][3])
                             : "r"(ad));
                uint32_t ad2 = as_l_base + (uint32_t)(row * AS + col) * 2;
                asm volatile("ldmatrix.sync.aligned.m8n8.x4.shared.b16 {%0,%1,%2,%3}, [%4];"
                             : "=r"(al[mi][0]), "=r"(al[mi][1]), "=r"(al[mi][2]), "=r"(al[mi][3])
                             : "r"(ad2));
            }
#pragma unroll
            for (int ni = 0; ni < 4; ni++) {
                int row = k16 + (lane & 15);
                int col = warp_n * 32 + ni * 8;
                uint32_t bd = bs_h_base + (uint32_t)(row * BS + col) * 2;
                asm volatile("ldmatrix.sync.aligned.m8n8.x2.trans.shared.b16 {%0,%1}, [%2];"
                             : "=r"(bh[ni][0]), "=r"(bh[ni][1]) : "r"(bd));
                uint32_t bd2 = bs_l_base + (uint32_t)(row * BS + col) * 2;
                asm volatile("ldmatrix.sync.aligned.m8n8.x2.trans.shared.b16 {%0,%1}, [%2];"
                             : "=r"(bl[ni][0]), "=r"(bl[ni][1]) : "r"(bd2));
            }
#pragma unroll
            for (int mi = 0; mi < 2; mi++) {
#pragma unroll
                for (int ni = 0; ni < 4; ni++) {
                    MMA_F16(acc[mi][ni], ah[mi], bh[ni]);
                    MMA_F16(acc[mi][ni], ah[mi], bl[ni]);
                    MMA_F16(acc[mi][ni], al[mi], bh[ni]);
                }
            }
        }
        __syncthreads();
    }

    // epilogue: bias + relu + store (fp16 or fp32)
#pragma unroll
    for (int mi = 0; mi < 2; mi++) {
#pragma unroll
        for (int ni = 0; ni < 4; ni++) {
            int r0 = bm + warp_m * 32 + mi * 16 + (lane >> 2);
            int c0 = bn + warp_n * 32 + ni * 8 + (lane & 3) * 2;
            float b0 = bias[c0], b1 = bias[c0 + 1];
            float* d = acc[mi][ni];
            float2 v0 = make_float2(fmaxf(d[0] + b0, 0.f), fmaxf(d[1] + b1, 0.f));
            float2 v1 = make_float2(fmaxf(d[2] + b0, 0.f), fmaxf(d[3] + b1, 0.f));
            if (OUT_HALF) {
                __half* C = (__half*)Cv;
                if (r0 < M)
                    *(__half2*)&C[(size_t)r0 * D + c0] = __floats2half2_rn(v0.x, v0.y);
                if (r0 + 8 < M)
                    *(__half2*)&C[(size_t)(r0 + 8) * D + c0] = __floats2half2_rn(v1.x, v1.y);
            } else {
                float* C = (float*)Cv;
                if (r0 < M) *(float2*)&C[(size_t)r0 * D + c0] = v0;
                if (r0 + 8 < M) *(float2*)&C[(size_t)(r0 + 8) * D + c0] = v1;
            }
        }
    }
}

// ---------------- driver ----------------
extern "C" void kernel_launch(void* const* d_in, const int* in_sizes, int n_in,
                              void* d_out, int out_size) {
    const float* x = (const float*)d_in[0];
    const int* ei = (const int*)d_in[1];   // int32 (JAX x64 disabled)
    const float* g0 = (const float*)d_in[2];
    const float* b0 = (const float*)d_in[3];
    const float* W1a = (const float*)d_in[4];
    const float* b1a = (const float*)d_in[5];
    const float* g1 = (const float*)d_in[6];
    const float* bt1 = (const float*)d_in[7];
    const float* W1b = (const float*)d_in[8];
    const float* b1b = (const float*)d_in[9];
    const float* W2a = (const float*)d_in[10];
    const float* b2a = (const float*)d_in[11];
    const float* g2 = (const float*)d_in[12];
    const float* bt2 = (const float*)d_in[13];
    const float* W2b = (const float*)d_in[14];
    const float* b2b = (const float*)d_in[15];
    float* out = (float*)d_out;

    int M = in_sizes[0] / D;
    int E = in_sizes[1] / 2;
    const int* srcI = ei;
    const int* dstI = ei + E;

    __half *t, *xh, *hh;
    float* u;
    cudaGetSymbolAddress((void**)&t, g_t);
    cudaGetSymbolAddress((void**)&u, g_u);
    cudaGetSymbolAddress((void**)&xh, g_xh);
    cudaGetSymbolAddress((void**)&hh, g_hh);
    __half *wh, *wl;
    cudaGetSymbolAddress((void**)&wh, g_wh);
    cudaGetSymbolAddress((void**)&wl, g_wl);
    __half* Wh[4] = {wh, wh + D * D, wh + 2 * D * D, wh + 3 * D * D};
    __half* Wl[4] = {wl, wl + D * D, wl + 2 * D * D, wl + 3 * D * D};

    dim3 gemmGrid((M + 127) / 128, 2);
    int aggGrid = (M + 7) / 8;
    int nb = (M + SCANB - 1) / SCANB;

    // ---- pre-convert weights (one launch for all 4) ----
    convert_w_kernel<<<dim3((D * D / 2) / 256, 4), 256>>>(W1a, W1b, W2a, W2b);

    // ---- build CSR once (reused by both convs) ----
    zero_deg_kernel<<<(M + 255) / 256, 256>>>(M);
    hist_kernel<<<(E + 255) / 256, 256>>>(dstI, E);
    scan_block_kernel<<<nb, SCANB>>>(M);
    scan_bsum_kernel<<<1, 32>>>(nb);
    scan_add_kernel<<<nb, SCANB>>>(M, E);
    fill_kernel<<<(E + 255) / 256, 256>>>(srcI, dstI, E);

    // ---- BN0 stats on x (+ fp16 copy); agg with BN folded ----
    zero_stats_kernel<<<1, 256>>>();
    stats_kernel<1><<<1024, 256>>>(x, xh, M);
    finalize_stats_kernel<<<1, 256>>>(g0, b0, M);
    agg_csr_half_kernel<1><<<aggGrid, 256>>>(xh, t, M);                 // t = BN0-agg(x)

    // ---- conv1 ----
    gemm_a_kernel<<<gemmGrid, 512>>>(t, Wh[0], Wl[0], b1a, u, M);       // u = t@W1a+b (fp32)
    zero_stats_kernel<<<1, 256>>>();
    stats_kernel<0><<<1024, 256>>>(u, nullptr, M);
    finalize_stats_kernel<<<1, 256>>>(g1, bt1, M);
    gemm_b_kernel<1><<<gemmGrid, 512>>>(u, Wh[1], Wl[1], b1b, hh, M);   // h fp16

    // ---- conv2 ----
    agg_csr_half_kernel<0><<<aggGrid, 256>>>(hh, t, M);                 // t = h + Σh
    gemm_a_kernel<<<gemmGrid, 512>>>(t, Wh[2], Wl[2], b2a, u, M);
    zero_stats_kernel<<<1, 256>>>();
    stats_kernel<0><<<1024, 256>>>(u, nullptr, M);
    finalize_stats_kernel<<<1, 256>>>(g2, bt2, M);
    gemm_b_kernel<0><<<gemmGrid, 512>>>(u, Wh[3], Wl[3], b2b, out, M);  // out fp32
}

// round 16
// speedup vs baseline: 1.4716x; 1.4716x over previous
#include <cuda_runtime.h>
#include <cuda_bf16.h>
#include <cuda_fp16.h>
#include <cstdint>

#define D 256
#define MAXM 100096   // >= N, multiple of 128
#define MAXE 1700000
#define SCANB 1024
#define MAXSB 128

// ---------------- scratch (device globals; no allocations) ----------------
__device__ __half g_t[(size_t)MAXM * D];   // aggregated features (fp16, GEMM-a input)
__device__ __half g_u[(size_t)MAXM * D];   // GEMM-a output (fp16)
__device__ __half g_xh[(size_t)MAXM * D];  // fp16 copy of x (gather source)
__device__ __half g_hh[(size_t)MAXM * D];  // conv1 output h (fp16, gather source)
__device__ float g_sum[D];
__device__ float g_sumsq[D];
__device__ float g_scale[D];
__device__ float g_shift[D];
// weights: bf16 hi/lo (for 3-term GEMM-b) AND fp16 hi/lo (for 2-term GEMM-a)
__device__ __nv_bfloat16 g_wh[4][D * D];
__device__ __nv_bfloat16 g_wl[4][D * D];
__device__ __half g_fh[4][D * D];
__device__ __half g_fl[4][D * D];
// CSR scratch
__device__ int g_deg[MAXM];
__device__ int g_cursor[MAXM];
__device__ int g_rowptr[MAXM + 1];
__device__ int g_col[MAXE];
__device__ int g_bsum[MAXSB];

// ---------------- BN helpers ----------------
__global__ void zero_stats_kernel() {
    g_sum[threadIdx.x] = 0.f;
    g_sumsq[threadIdx.x] = 0.f;
}

// fp32 input stats (+ optional fused fp16 copy)
template <int WRITE_H>
__global__ void stats_kernel(const float* __restrict__ X, __half* __restrict__ XH,
                             int M) {
    int c = threadIdx.x;
    int rows = (M + gridDim.x - 1) / gridDim.x;
    int r0 = blockIdx.x * rows;
    int r1 = r0 + rows;
    if (r1 > M) r1 = M;
    float s = 0.f, q = 0.f;
    int r = r0;
    for (; r + 4 <= r1; r += 4) {
        float v0 = X[(size_t)(r + 0) * D + c];
        float v1 = X[(size_t)(r + 1) * D + c];
        float v2 = X[(size_t)(r + 2) * D + c];
        float v3 = X[(size_t)(r + 3) * D + c];
        s += (v0 + v1) + (v2 + v3);
        q += (v0 * v0 + v1 * v1) + (v2 * v2 + v3 * v3);
        if (WRITE_H) {
            XH[(size_t)(r + 0) * D + c] = __float2half_rn(v0);
            XH[(size_t)(r + 1) * D + c] = __float2half_rn(v1);
            XH[(size_t)(r + 2) * D + c] = __float2half_rn(v2);
            XH[(size_t)(r + 3) * D + c] = __float2half_rn(v3);
        }
    }
    for (; r < r1; r++) {
        float v = X[(size_t)r * D + c];
        s += v;
        q += v * v;
        if (WRITE_H) XH[(size_t)r * D + c] = __float2half_rn(v);
    }
    if (r1 > r0) {
        atomicAdd(&g_sum[c], s);
        atomicAdd(&g_sumsq[c], q);
    }
}

// fp16 input stats (for u)
__global__ void stats_half_kernel(const __half* __restrict__ X, int M) {
    int c = threadIdx.x;
    int rows = (M + gridDim.x - 1) / gridDim.x;
    int r0 = blockIdx.x * rows;
    int r1 = r0 + rows;
    if (r1 > M) r1 = M;
    float s = 0.f, q = 0.f;
    int r = r0;
    for (; r + 4 <= r1; r += 4) {
        float v0 = __half2float(X[(size_t)(r + 0) * D + c]);
        float v1 = __half2float(X[(size_t)(r + 1) * D + c]);
        float v2 = __half2float(X[(size_t)(r + 2) * D + c]);
        float v3 = __half2float(X[(size_t)(r + 3) * D + c]);
        s += (v0 + v1) + (v2 + v3);
        q += (v0 * v0 + v1 * v1) + (v2 * v2 + v3 * v3);
    }
    for (; r < r1; r++) {
        float v = __half2float(X[(size_t)r * D + c]);
        s += v;
        q += v * v;
    }
    if (r1 > r0) {
        atomicAdd(&g_sum[c], s);
        atomicAdd(&g_sumsq[c], q);
    }
}

__global__ void finalize_stats_kernel(const float* __restrict__ gamma,
                                      const float* __restrict__ beta, int M) {
    int c = threadIdx.x;
    float invM = 1.f / (float)M;
    float mu = g_sum[c] * invM;
    float var = g_sumsq[c] * invM - mu * mu;
    float sc = gamma[c] * rsqrtf(var + 1e-5f);
    g_scale[c] = sc;
    g_shift[c] = beta[c] - mu * sc;
}

// ---------------- weight pre-conversion: bf16 hi/lo AND fp16 hi/lo ----------
__global__ void convert_w_kernel(const float* __restrict__ W0,
                                 const float* __restrict__ W1,
                                 const float* __restrict__ W2,
                                 const float* __restrict__ W3) {
    const float* Ws[4] = {W0, W1, W2, W3};
    int w = blockIdx.y;
    int i = blockIdx.x * blockDim.x + threadIdx.x;  // over D*D/2 pairs
    float2 v = ((const float2*)Ws[w])[i];
    __nv_bfloat162 bh = __floats2bfloat162_rn(v.x, v.y);
    float2 bf = __bfloat1622float2(bh);
    __nv_bfloat162 bl = __floats2bfloat162_rn(v.x - bf.x, v.y - bf.y);
    ((__nv_bfloat162*)g_wh[w])[i] = bh;
    ((__nv_bfloat162*)g_wl[w])[i] = bl;
    __half2 fh = __floats2half2_rn(v.x, v.y);
    float2 ff = __half22float2(fh);
    __half2 fl = __floats2half2_rn(v.x - ff.x, v.y - ff.y);
    ((__half2*)g_fh[w])[i] = fh;
    ((__half2*)g_fl[w])[i] = fl;
}

// ---------------- CSR build ----------------
__global__ void zero_deg_kernel(int M) {
    int i = blockIdx.x * blockDim.x + threadIdx.x;
    if (i < M) {
        g_deg[i] = 0;
        g_cursor[i] = 0;
    }
}

__global__ void hist_kernel(const int* __restrict__ dstIdx, int E) {
    int e = blockIdx.x * blockDim.x + threadIdx.x;
    if (e < E) atomicAdd(&g_deg[dstIdx[e]], 1);
}

__global__ void scan_block_kernel(int M) {
    __shared__ int sh[SCANB];
    int i = blockIdx.x * SCANB + threadIdx.x;
    int v = (i < M) ? g_deg[i] : 0;
    sh[threadIdx.x] = v;
    __syncthreads();
    for (int off = 1; off < SCANB; off <<= 1) {
        int t = (threadIdx.x >= off) ? sh[threadIdx.x - off] : 0;
        __syncthreads();
        sh[threadIdx.x] += t;
        __syncthreads();
    }
    if (i < M) g_rowptr[i] = sh[threadIdx.x] - v;
    if (threadIdx.x == SCANB - 1) g_bsum[blockIdx.x] = sh[SCANB - 1];
}

__global__ void scan_bsum_kernel(int nb) {
    if (threadIdx.x == 0) {
        int run = 0;
        for (int i = 0; i < nb; i++) {
            int v = g_bsum[i];
            g_bsum[i] = run;
            run += v;
        }
    }
}

__global__ void scan_add_kernel(int M, int E) {
    int i = blockIdx.x * SCANB + threadIdx.x;
    if (i < M) g_rowptr[i] += g_bsum[blockIdx.x];
    if (i == 0) g_rowptr[M] = E;
}

__global__ void fill_kernel(const int* __restrict__ srcIdx,
                            const int* __restrict__ dstIdx, int E) {
    int e = blockIdx.x * blockDim.x + threadIdx.x;
    if (e >= E) return;
    int d = dstIdx[e];
    int pos = g_rowptr[d] + atomicAdd(&g_cursor[d], 1);
    g_col[pos] = srcIdx[e];
}

// ---------------- CSR aggregation (fp16 src, fp16 out, MLP=4) ----------------
template <int BN_FOLD>
__global__ void agg_csr_half_kernel(const __half* __restrict__ feat,
                                    __half* __restrict__ out, int M) {
    int node = blockIdx.x * 8 + (threadIdx.x >> 5);
    if (node >= M) return;
    int lane = threadIdx.x & 31;
    int e0 = __ldg(&g_rowptr[node]);
    int e1 = __ldg(&g_rowptr[node + 1]);
    const uint4* base = (const uint4*)feat;

    float acc[8];
    {
        uint4 v = base[(size_t)node * 32 + lane];
        const __half2* h2 = (const __half2*)&v;
#pragma unroll
        for (int p = 0; p < 4; p++) {
            float2 f = __half22float2(h2[p]);
            acc[p * 2] = f.x;
            acc[p * 2 + 1] = f.y;
        }
    }
    int e = e0;
    for (; e + 4 <= e1; e += 4) {
        int s0 = __ldg(&g_col[e + 0]);
        int s1 = __ldg(&g_col[e + 1]);
        int s2 = __ldg(&g_col[e + 2]);
        int s3 = __ldg(&g_col[e + 3]);
        uint4 v0 = base[(size_t)s0 * 32 + lane];
        uint4 v1 = base[(size_t)s1 * 32 + lane];
        uint4 v2 = base[(size_t)s2 * 32 + lane];
        uint4 v3 = base[(size_t)s3 * 32 + lane];
        const __half2* a2 = (const __half2*)&v0;
        const __half2* b2 = (const __half2*)&v1;
        const __half2* c2 = (const __half2*)&v2;
        const __half2* d2 = (const __half2*)&v3;
#pragma unroll
        for (int p = 0; p < 4; p++) {
            float2 fa = __half22float2(a2[p]);
            float2 fb = __half22float2(b2[p]);
            float2 fc = __half22float2(c2[p]);
            float2 fd = __half22float2(d2[p]);
            acc[p * 2] += (fa.x + fb.x) + (fc.x + fd.x);
            acc[p * 2 + 1] += (fa.y + fb.y) + (fc.y + fd.y);
        }
    }
    for (; e < e1; e++) {
        int s = __ldg(&g_col[e]);
        uint4 v = base[(size_t)s * 32 + lane];
        const __half2* h2 = (const __half2*)&v;
#pragma unroll
        for (int p = 0; p < 4; p++) {
            float2 f = __half22float2(h2[p]);
            acc[p * 2] += f.x;
            acc[p * 2 + 1] += f.y;
        }
    }
    if (BN_FOLD) {
        float k = (float)(1 + (e1 - e0));
#pragma unroll
        for (int p = 0; p < 8; p++) {
            int c = lane * 8 + p;
            acc[p] = acc[p] * g_scale[c] + k * g_shift[c];
        }
    }
    uint4 o;
    __half2* o2 = (__half2*)&o;
#pragma unroll
    for (int p = 0; p < 4; p++)
        o2[p] = __floats2half2_rn(acc[p * 2], acc[p * 2 + 1]);
    ((uint4*)out)[(size_t)node * 32 + lane] = o;
}

// ---------------- common GEMM geometry ----------------
#define BK 32
#define AS 40    // As row stride (b16 elements)
#define BS 136   // Bs row stride (b16 elements)
#define NKT (D / BK)   // 8

// ---------------- GEMM-A: A fp16 exact, fp16 weights, 2-term ---------------
// u = t @ (wh + wl) + bias ; output fp16 (feeds stats + GEMM-b)
__global__ __launch_bounds__(512, 1) void gemm_a_kernel(
    const __half* __restrict__ A, const __half* __restrict__ Wh,
    const __half* __restrict__ Wl, const float* __restrict__ bias,
    __half* __restrict__ C, int M) {
    __shared__ __half As[128 * AS];
    __shared__ __half Bs_h[BK * BS];
    __shared__ __half Bs_l[BK * BS];

    int bm = blockIdx.x * 128;
    int bn = blockIdx.y * 128;
    int tid = threadIdx.x;
    int lane = tid & 31;
    int wid = tid >> 5;
    int warp_m = wid >> 2;   // 0..3
    int warp_n = wid & 3;    // 0..3

    float acc[2][4][4];
#pragma unroll
    for (int i = 0; i < 2; i++)
#pragma unroll
        for (int j = 0; j < 4; j++)
#pragma unroll
            for (int r = 0; r < 4; r++) acc[i][j][r] = 0.f;

    int a_row = tid >> 2;
    int a_kh = (tid & 3) * 8;
    bool a_valid = (bm + a_row) < M;
    int b_row = tid >> 4;
    int b_c8 = (tid & 15) * 8;

    uint32_t as_base = (uint32_t)__cvta_generic_to_shared(As);
    uint32_t bs_h_base = (uint32_t)__cvta_generic_to_shared(Bs_h);
    uint32_t bs_l_base = (uint32_t)__cvta_generic_to_shared(Bs_l);

    uint4 a_pf, bh_pf, bl_pf;
    auto load_g = [&](int k0) {
        a_pf = a_valid ? *(const uint4*)(A + (size_t)(bm + a_row) * D + k0 + a_kh)
                       : make_uint4(0u, 0u, 0u, 0u);
        size_t goff = (size_t)(k0 + b_row) * D + bn + b_c8;
        bh_pf = *(const uint4*)(Wh + goff);
        bl_pf = *(const uint4*)(Wl + goff);
    };

    load_g(0);
    for (int kt = 0; kt < NKT; kt++) {
        *(uint4*)&As[a_row * AS + a_kh] = a_pf;
        *(uint4*)&Bs_h[b_row * BS + b_c8] = bh_pf;
        *(uint4*)&Bs_l[b_row * BS + b_c8] = bl_pf;
        __syncthreads();
        if (kt + 1 < NKT) load_g((kt + 1) * BK);

#pragma unroll
        for (int k16 = 0; k16 < BK; k16 += 16) {
            uint32_t ah[2][4];
            uint32_t bh[4][2];
            uint32_t bl[4][2];
#pragma unroll
            for (int mi = 0; mi < 2; mi++) {
                int row = warp_m * 32 + mi * 16 + (lane & 15);
                int col = k16 + ((lane >> 4) << 3);
                uint32_t ad = as_base + (uint32_t)(row * AS + col) * 2;
                asm volatile("ldmatrix.sync.aligned.m8n8.x4.shared.b16 {%0,%1,%2,%3}, [%4];"
                             : "=r"(ah[mi][0]), "=r"(ah[mi][1]), "=r"(ah[mi][2]), "=r"(ah[mi][3])
                             : "r"(ad));
            }
#pragma unroll
            for (int ni = 0; ni < 4; ni++) {
                int row = k16 + (lane & 15);
                int col = warp_n * 32 + ni * 8;
                uint32_t bd = bs_h_base + (uint32_t)(row * BS + col) * 2;
                asm volatile("ldmatrix.sync.aligned.m8n8.x2.trans.shared.b16 {%0,%1}, [%2];"
                             : "=r"(bh[ni][0]), "=r"(bh[ni][1]) : "r"(bd));
                uint32_t bd2 = bs_l_base + (uint32_t)(row * BS + col) * 2;
                asm volatile("ldmatrix.sync.aligned.m8n8.x2.trans.shared.b16 {%0,%1}, [%2];"
                             : "=r"(bl[ni][0]), "=r"(bl[ni][1]) : "r"(bd2));
            }
#pragma unroll
            for (int mi = 0; mi < 2; mi++) {
#pragma unroll
                for (int ni = 0; ni < 4; ni++) {
                    float* d = acc[mi][ni];
                    asm volatile(
                        "mma.sync.aligned.m16n8k16.row.col.f32.f16.f16.f32 "
                        "{%0,%1,%2,%3}, {%4,%5,%6,%7}, {%8,%9}, {%0,%1,%2,%3};"
                        : "+f"(d[0]), "+f"(d[1]), "+f"(d[2]), "+f"(d[3])
                        : "r"(ah[mi][0]), "r"(ah[mi][1]), "r"(ah[mi][2]), "r"(ah[mi][3]),
                          "r"(bh[ni][0]), "r"(bh[ni][1]));
                    asm volatile(
                        "mma.sync.aligned.m16n8k16.row.col.f32.f16.f16.f32 "
                        "{%0,%1,%2,%3}, {%4,%5,%6,%7}, {%8,%9}, {%0,%1,%2,%3};"
                        : "+f"(d[0]), "+f"(d[1]), "+f"(d[2]), "+f"(d[3])
                        : "r"(ah[mi][0]), "r"(ah[mi][1]), "r"(ah[mi][2]), "r"(ah[mi][3]),
                          "r"(bl[ni][0]), "r"(bl[ni][1]));
                }
            }
        }
        __syncthreads();
    }

    // epilogue: bias + fp16 store (no relu: feeds BN stats)
#pragma unroll
    for (int mi = 0; mi < 2; mi++) {
#pragma unroll
        for (int ni = 0; ni < 4; ni++) {
            int r0 = bm + warp_m * 32 + mi * 16 + (lane >> 2);
            int c0 = bn + warp_n * 32 + ni * 8 + (lane & 3) * 2;
            float b0 = bias[c0], b1 = bias[c0 + 1];
            float* d = acc[mi][ni];
            if (r0 < M)
                *(__half2*)&C[(size_t)r0 * D + c0] =
                    __floats2half2_rn(d[0] + b0, d[1] + b1);
            if (r0 + 8 < M)
                *(__half2*)&C[(size_t)(r0 + 8) * D + c0] =
                    __floats2half2_rn(d[2] + b0, d[3] + b1);
        }
    }
}

// ---------------- GEMM-B (R14's kernel): A fp16 + BN/relu, bf16x3 ----------
template <int OUT_HALF>
__global__ __launch_bounds__(512, 1) void gemm_b_kernel(
    const __half* __restrict__ A, const __nv_bfloat16* __restrict__ Wh,
    const __nv_bfloat16* __restrict__ Wl, const float* __restrict__ bias,
    void* __restrict__ Cv, int M) {
    __shared__ __nv_bfloat16 As_h[128 * AS];
    __shared__ __nv_bfloat16 As_l[128 * AS];
    __shared__ __nv_bfloat16 Bs_h[BK * BS];
    __shared__ __nv_bfloat16 Bs_l[BK * BS];

    int bm = blockIdx.x * 128;
    int bn = blockIdx.y * 128;
    int tid = threadIdx.x;
    int lane = tid & 31;
    int wid = tid >> 5;
    int warp_m = wid >> 2;
    int warp_n = wid & 3;

    float acc[2][4][4];
#pragma unroll
    for (int i = 0; i < 2; i++)
#pragma unroll
        for (int j = 0; j < 4; j++)
#pragma unroll
            for (int r = 0; r < 4; r++) acc[i][j][r] = 0.f;

    int a_row = tid >> 2;
    int a_kh = (tid & 3) * 8;
    bool a_valid = (bm + a_row) < M;
    int b_row = tid >> 4;
    int b_c8 = (tid & 15) * 8;

    uint32_t as_h_base = (uint32_t)__cvta_generic_to_shared(As_h);
    uint32_t as_l_base = (uint32_t)__cvta_generic_to_shared(As_l);
    uint32_t bs_h_base = (uint32_t)__cvta_generic_to_shared(Bs_h);
    uint32_t bs_l_base = (uint32_t)__cvta_generic_to_shared(Bs_l);

    uint4 a_pf, bh_pf, bl_pf;
    auto load_g = [&](int k0) {
        a_pf = a_valid ? *(const uint4*)(A + (size_t)(bm + a_row) * D + k0 + a_kh)
                       : make_uint4(0u, 0u, 0u, 0u);
        size_t goff = (size_t)(k0 + b_row) * D + bn + b_c8;
        bh_pf = *(const uint4*)(Wh + goff);
        bl_pf = *(const uint4*)(Wl + goff);
    };

    load_g(0);
    for (int kt = 0; kt < NKT; kt++) {
        int k0 = kt * BK;
        {
            const __half2* ah2 = (const __half2*)&a_pf;
            float f[8];
#pragma unroll
            for (int p = 0; p < 4; p++) {
                float2 t2 = __half22float2(ah2[p]);
                f[p * 2] = t2.x;
                f[p * 2 + 1] = t2.y;
            }
#pragma unroll
            for (int p = 0; p < 2; p++) {
                float4 s = ((const float4*)g_scale)[((k0 + a_kh) >> 2) + p];
                float4 sh = ((const float4*)g_shift)[((k0 + a_kh) >> 2) + p];
                f[p * 4 + 0] = fmaxf(f[p * 4 + 0] * s.x + sh.x, 0.f);
                f[p * 4 + 1] = fmaxf(f[p * 4 + 1] * s.y + sh.y, 0.f);
                f[p * 4 + 2] = fmaxf(f[p * 4 + 2] * s.z + sh.z, 0.f);
                f[p * 4 + 3] = fmaxf(f[p * 4 + 3] * s.w + sh.w, 0.f);
            }
            int off = a_row * AS + a_kh;
#pragma unroll
            for (int p = 0; p < 4; p++) {
                __nv_bfloat162 h2 = __floats2bfloat162_rn(f[p * 2], f[p * 2 + 1]);
                float2 fb = __bfloat1622float2(h2);
                __nv_bfloat162 l2 = __floats2bfloat162_rn(f[p * 2] - fb.x,
                                                          f[p * 2 + 1] - fb.y);
                *(__nv_bfloat162*)&As_h[off + p * 2] = h2;
                *(__nv_bfloat162*)&As_l[off + p * 2] = l2;
            }
            *(uint4*)&Bs_h[b_row * BS + b_c8] = bh_pf;
            *(uint4*)&Bs_l[b_row * BS + b_c8] = bl_pf;
        }
        __syncthreads();
        if (kt + 1 < NKT) load_g(k0 + BK);

#pragma unroll
        for (int k16 = 0; k16 < BK; k16 += 16) {
            uint32_t ah[2][4];
            uint32_t al[2][4];
            uint32_t bh[4][2];
            uint32_t bl[4][2];
#pragma unroll
            for (int mi = 0; mi < 2; mi++) {
                int row = warp_m * 32 + mi * 16 + (lane & 15);
                int col = k16 + ((lane >> 4) << 3);
                uint32_t ad = as_h_base + (uint32_t)(row * AS + col) * 2;
                asm volatile("ldmatrix.sync.aligned.m8n8.x4.shared.b16 {%0,%1,%2,%3}, [%4];"
                             : "=r"(ah[mi][0]), "=r"(ah[mi][1]), "=r"(ah[mi][2]), "=r"(ah[mi][3])
                             : "r"(ad));
                uint32_t ad2 = as_l_base + (uint32_t)(row * AS + col) * 2;
                asm volatile("ldmatrix.sync.aligned.m8n8.x4.shared.b16 {%0,%1,%2,%3}, [%4];"
                             : "=r"(al[mi][0]), "=r"(al[mi][1]), "=r"(al[mi][2]), "=r"(al[mi][3])
                             : "r"(ad2));
            }
#pragma unroll
            for (int ni = 0; ni < 4; ni++) {
                int row = k16 + (lane & 15);
                int col = warp_n * 32 + ni * 8;
                uint32_t bd = bs_h_base + (uint32_t)(row * BS + col) * 2;
                asm volatile("ldmatrix.sync.aligned.m8n8.x2.trans.shared.b16 {%0,%1}, [%2];"
                             : "=r"(bh[ni][0]), "=r"(bh[ni][1]) : "r"(bd));
                uint32_t bd2 = bs_l_base + (uint32_t)(row * BS + col) * 2;
                asm volatile("ldmatrix.sync.aligned.m8n8.x2.trans.shared.b16 {%0,%1}, [%2];"
                             : "=r"(bl[ni][0]), "=r"(bl[ni][1]) : "r"(bd2));
            }
#pragma unroll
            for (int mi = 0; mi < 2; mi++) {
#pragma unroll
                for (int ni = 0; ni < 4; ni++) {
                    float* d = acc[mi][ni];
                    asm volatile(
                        "mma.sync.aligned.m16n8k16.row.col.f32.bf16.bf16.f32 "
                        "{%0,%1,%2,%3}, {%4,%5,%6,%7}, {%8,%9}, {%0,%1,%2,%3};"
                        : "+f"(d[0]), "+f"(d[1]), "+f"(d[2]), "+f"(d[3])
                        : "r"(ah[mi][0]), "r"(ah[mi][1]), "r"(ah[mi][2]), "r"(ah[mi][3]),
                          "r"(bh[ni][0]), "r"(bh[ni][1]));
                    asm volatile(
                        "mma.sync.aligned.m16n8k16.row.col.f32.bf16.bf16.f32 "
                        "{%0,%1,%2,%3}, {%4,%5,%6,%7}, {%8,%9}, {%0,%1,%2,%3};"
                        : "+f"(d[0]), "+f"(d[1]), "+f"(d[2]), "+f"(d[3])
                        : "r"(ah[mi][0]), "r"(ah[mi][1]), "r"(ah[mi][2]), "r"(ah[mi][3]),
                          "r"(bl[ni][0]), "r"(bl[ni][1]));
                    asm volatile(
                        "mma.sync.aligned.m16n8k16.row.col.f32.bf16.bf16.f32 "
                        "{%0,%1,%2,%3}, {%4,%5,%6,%7}, {%8,%9}, {%0,%1,%2,%3};"
                        : "+f"(d[0]), "+f"(d[1]), "+f"(d[2]), "+f"(d[3])
                        : "r"(al[mi][0]), "r"(al[mi][1]), "r"(al[mi][2]), "r"(al[mi][3]),
                          "r"(bh[ni][0]), "r"(bh[ni][1]));
                }
            }
        }
        __syncthreads();
    }

#pragma unroll
    for (int mi = 0; mi < 2; mi++) {
#pragma unroll
        for (int ni = 0; ni < 4; ni++) {
            int r0 = bm + warp_m * 32 + mi * 16 + (lane >> 2);
            int c0 = bn + warp_n * 32 + ni * 8 + (lane & 3) * 2;
            float b0 = bias[c0], b1 = bias[c0 + 1];
            float* d = acc[mi][ni];
            float2 v0 = make_float2(fmaxf(d[0] + b0, 0.f), fmaxf(d[1] + b1, 0.f));
            float2 v1 = make_float2(fmaxf(d[2] + b0, 0.f), fmaxf(d[3] + b1, 0.f));
            if (OUT_HALF) {
                __half* C = (__half*)Cv;
                if (r0 < M)
                    *(__half2*)&C[(size_t)r0 * D + c0] = __floats2half2_rn(v0.x, v0.y);
                if (r0 + 8 < M)
                    *(__half2*)&C[(size_t)(r0 + 8) * D + c0] = __floats2half2_rn(v1.x, v1.y);
            } else {
                float* C = (float*)Cv;
                if (r0 < M) *(float2*)&C[(size_t)r0 * D + c0] = v0;
                if (r0 + 8 < M) *(float2*)&C[(size_t)(r0 + 8) * D + c0] = v1;
            }
        }
    }
}

// ---------------- driver ----------------
extern "C" void kernel_launch(void* const* d_in, const int* in_sizes, int n_in,
                              void* d_out, int out_size) {
    const float* x = (const float*)d_in[0];
    const int* ei = (const int*)d_in[1];   // int32 (JAX x64 disabled)
    const float* g0 = (const float*)d_in[2];
    const float* b0 = (const float*)d_in[3];
    const float* W1a = (const float*)d_in[4];
    const float* b1a = (const float*)d_in[5];
    const float* g1 = (const float*)d_in[6];
    const float* bt1 = (const float*)d_in[7];
    const float* W1b = (const float*)d_in[8];
    const float* b1b = (const float*)d_in[9];
    const float* W2a = (const float*)d_in[10];
    const float* b2a = (const float*)d_in[11];
    const float* g2 = (const float*)d_in[12];
    const float* bt2 = (const float*)d_in[13];
    const float* W2b = (const float*)d_in[14];
    const float* b2b = (const float*)d_in[15];
    float* out = (float*)d_out;

    int M = in_sizes[0] / D;
    int E = in_sizes[1] / 2;
    const int* srcI = ei;
    const int* dstI = ei + E;

    __half *t, *u, *xh, *hh;
    cudaGetSymbolAddress((void**)&t, g_t);
    cudaGetSymbolAddress((void**)&u, g_u);
    cudaGetSymbolAddress((void**)&xh, g_xh);
    cudaGetSymbolAddress((void**)&hh, g_hh);
    __nv_bfloat16 *wh, *wl;
    cudaGetSymbolAddress((void**)&wh, g_wh);
    cudaGetSymbolAddress((void**)&wl, g_wl);
    __half *fh, *fl;
    cudaGetSymbolAddress((void**)&fh, g_fh);
    cudaGetSymbolAddress((void**)&fl, g_fl);
    __nv_bfloat16* Wh[4] = {wh, wh + D * D, wh + 2 * D * D, wh + 3 * D * D};
    __nv_bfloat16* Wl[4] = {wl, wl + D * D, wl + 2 * D * D, wl + 3 * D * D};
    __half* Fh[4] = {fh, fh + D * D, fh + 2 * D * D, fh + 3 * D * D};
    __half* Fl[4] = {fl, fl + D * D, fl + 2 * D * D, fl + 3 * D * D};

    dim3 gemmGrid((M + 127) / 128, 2);
    int aggGrid = (M + 7) / 8;
    int nb = (M + SCANB - 1) / SCANB;

    // ---- pre-convert weights (one launch for all 4, both formats) ----
    convert_w_kernel<<<dim3((D * D / 2) / 256, 4), 256>>>(W1a, W1b, W2a, W2b);

    // ---- build CSR once (reused by both convs) ----
    zero_deg_kernel<<<(M + 255) / 256, 256>>>(M);
    hist_kernel<<<(E + 255) / 256, 256>>>(dstI, E);
    scan_block_kernel<<<nb, SCANB>>>(M);
    scan_bsum_kernel<<<1, 32>>>(nb);
    scan_add_kernel<<<nb, SCANB>>>(M, E);
    fill_kernel<<<(E + 255) / 256, 256>>>(srcI, dstI, E);

    // ---- BN0 stats on x (+ fp16 copy); agg with BN folded ----
    zero_stats_kernel<<<1, 256>>>();
    stats_kernel<1><<<512, 256>>>(x, xh, M);
    finalize_stats_kernel<<<1, 256>>>(g0, b0, M);
    agg_csr_half_kernel<1><<<aggGrid, 256>>>(xh, t, M);                 // t = BN0-agg(x)

    // ---- conv1 ----
    gemm_a_kernel<<<gemmGrid, 512>>>(t, Fh[0], Fl[0], b1a, u, M);       // u = t@W1a+b
    zero_stats_kernel<<<1, 256>>>();
    stats_half_kernel<<<512, 256>>>(u, M);
    finalize_stats_kernel<<<1, 256>>>(g1, bt1, M);
    gemm_b_kernel<1><<<gemmGrid, 512>>>(u, Wh[1], Wl[1], b1b, hh, M);   // h fp16

    // ---- conv2 ----
    agg_csr_half_kernel<0><<<aggGrid, 256>>>(hh, t, M);                 // t = h + Σh
    gemm_a_kernel<<<gemmGrid, 512>>>(t, Fh[2], Fl[2], b2a, u, M);
    zero_stats_kernel<<<1, 256>>>();
    stats_half_kernel<<<512, 256>>>(u, M);
    finalize_stats_kernel<<<1, 256>>>(g2, bt2, M);
    gemm_b_kernel<0><<<gemmGrid, 512>>>(u, Wh[3], Wl[3], b2b, out, M);  // out fp32
}

// round 17
// speedup vs baseline: 1.5127x; 1.0280x over previous
#include <cuda_runtime.h>
#include <cuda_bf16.h>
#include <cuda_fp16.h>
#include <cstdint>

#define D 256
#define MAXM 100096   // >= N, multiple of 128
#define MAXE 1700000
#define SCANB 1024
#define MAXSB 128

// ---------------- scratch (device globals; no allocations) ----------------
__device__ __half g_t[(size_t)MAXM * D];   // aggregated features (fp16, GEMM-a input)
__device__ __half g_u[(size_t)MAXM * D];   // GEMM-a output (fp16)
__device__ __half g_xh[(size_t)MAXM * D];  // fp16 copy of x (gather source)
__device__ __half g_hh[(size_t)MAXM * D];  // conv1 output h (fp16, gather source)
__device__ float g_sum[D];
__device__ float g_sumsq[D];
__device__ float g_scale[D];
__device__ float g_shift[D];
// weights: bf16 hi/lo (for 3-term GEMM-b) AND fp16 hi/lo (for 2-term GEMM-a)
__device__ __nv_bfloat16 g_wh[4][D * D];
__device__ __nv_bfloat16 g_wl[4][D * D];
__device__ __half g_fh[4][D * D];
__device__ __half g_fl[4][D * D];
// CSR scratch
__device__ int g_deg[MAXM];
__device__ int g_cursor[MAXM];
__device__ int g_rowptr[MAXM + 1];
__device__ int g_col[MAXE];
__device__ int g_bsum[MAXSB];

// ---------------- BN helpers ----------------
__global__ void zero_stats_kernel() {
    g_sum[threadIdx.x] = 0.f;
    g_sumsq[threadIdx.x] = 0.f;
}

template <int WRITE_H>
__global__ void stats_kernel(const float* __restrict__ X, __half* __restrict__ XH,
                             int M) {
    int c = threadIdx.x;
    int rows = (M + gridDim.x - 1) / gridDim.x;
    int r0 = blockIdx.x * rows;
    int r1 = r0 + rows;
    if (r1 > M) r1 = M;
    float s = 0.f, q = 0.f;
    int r = r0;
    for (; r + 4 <= r1; r += 4) {
        float v0 = X[(size_t)(r + 0) * D + c];
        float v1 = X[(size_t)(r + 1) * D + c];
        float v2 = X[(size_t)(r + 2) * D + c];
        float v3 = X[(size_t)(r + 3) * D + c];
        s += (v0 + v1) + (v2 + v3);
        q += (v0 * v0 + v1 * v1) + (v2 * v2 + v3 * v3);
        if (WRITE_H) {
            XH[(size_t)(r + 0) * D + c] = __float2half_rn(v0);
            XH[(size_t)(r + 1) * D + c] = __float2half_rn(v1);
            XH[(size_t)(r + 2) * D + c] = __float2half_rn(v2);
            XH[(size_t)(r + 3) * D + c] = __float2half_rn(v3);
        }
    }
    for (; r < r1; r++) {
        float v = X[(size_t)r * D + c];
        s += v;
        q += v * v;
        if (WRITE_H) XH[(size_t)r * D + c] = __float2half_rn(v);
    }
    if (r1 > r0) {
        atomicAdd(&g_sum[c], s);
        atomicAdd(&g_sumsq[c], q);
    }
}

__global__ void stats_half_kernel(const __half* __restrict__ X, int M) {
    int c = threadIdx.x;
    int rows = (M + gridDim.x - 1) / gridDim.x;
    int r0 = blockIdx.x * rows;
    int r1 = r0 + rows;
    if (r1 > M) r1 = M;
    float s = 0.f, q = 0.f;
    int r = r0;
    for (; r + 4 <= r1; r += 4) {
        float v0 = __half2float(X[(size_t)(r + 0) * D + c]);
        float v1 = __half2float(X[(size_t)(r + 1) * D + c]);
        float v2 = __half2float(X[(size_t)(r + 2) * D + c]);
        float v3 = __half2float(X[(size_t)(r + 3) * D + c]);
        s += (v0 + v1) + (v2 + v3);
        q += (v0 * v0 + v1 * v1) + (v2 * v2 + v3 * v3);
    }
    for (; r < r1; r++) {
        float v = __half2float(X[(size_t)r * D + c]);
        s += v;
        q += v * v;
    }
    if (r1 > r0) {
        atomicAdd(&g_sum[c], s);
        atomicAdd(&g_sumsq[c], q);
    }
}

__global__ void finalize_stats_kernel(const float* __restrict__ gamma,
                                      const float* __restrict__ beta, int M) {
    int c = threadIdx.x;
    float invM = 1.f / (float)M;
    float mu = g_sum[c] * invM;
    float var = g_sumsq[c] * invM - mu * mu;
    float sc = gamma[c] * rsqrtf(var + 1e-5f);
    g_scale[c] = sc;
    g_shift[c] = beta[c] - mu * sc;
}

// ---------------- weight pre-conversion: bf16 hi/lo AND fp16 hi/lo ----------
__global__ void convert_w_kernel(const float* __restrict__ W0,
                                 const float* __restrict__ W1,
                                 const float* __restrict__ W2,
                                 const float* __restrict__ W3) {
    const float* Ws[4] = {W0, W1, W2, W3};
    int w = blockIdx.y;
    int i = blockIdx.x * blockDim.x + threadIdx.x;  // over D*D/2 pairs
    float2 v = ((const float2*)Ws[w])[i];
    __nv_bfloat162 bh = __floats2bfloat162_rn(v.x, v.y);
    float2 bf = __bfloat1622float2(bh);
    __nv_bfloat162 bl = __floats2bfloat162_rn(v.x - bf.x, v.y - bf.y);
    ((__nv_bfloat162*)g_wh[w])[i] = bh;
    ((__nv_bfloat162*)g_wl[w])[i] = bl;
    __half2 fh = __floats2half2_rn(v.x, v.y);
    float2 ff = __half22float2(fh);
    __half2 fl = __floats2half2_rn(v.x - ff.x, v.y - ff.y);
    ((__half2*)g_fh[w])[i] = fh;
    ((__half2*)g_fl[w])[i] = fl;
}

// ---------------- CSR build ----------------
__global__ void zero_deg_kernel(int M) {
    int i = blockIdx.x * blockDim.x + threadIdx.x;
    if (i < M) {
        g_deg[i] = 0;
        g_cursor[i] = 0;
    }
}

__global__ void hist_kernel(const int* __restrict__ dstIdx, int E) {
    int e = blockIdx.x * blockDim.x + threadIdx.x;
    if (e < E) atomicAdd(&g_deg[dstIdx[e]], 1);
}

__global__ void scan_block_kernel(int M) {
    __shared__ int sh[SCANB];
    int i = blockIdx.x * SCANB + threadIdx.x;
    int v = (i < M) ? g_deg[i] : 0;
    sh[threadIdx.x] = v;
    __syncthreads();
    for (int off = 1; off < SCANB; off <<= 1) {
        int t = (threadIdx.x >= off) ? sh[threadIdx.x - off] : 0;
        __syncthreads();
        sh[threadIdx.x] += t;
        __syncthreads();
    }
    if (i < M) g_rowptr[i] = sh[threadIdx.x] - v;
    if (threadIdx.x == SCANB - 1) g_bsum[blockIdx.x] = sh[SCANB - 1];
}

__global__ void scan_bsum_kernel(int nb) {
    if (threadIdx.x == 0) {
        int run = 0;
        for (int i = 0; i < nb; i++) {
            int v = g_bsum[i];
            g_bsum[i] = run;
            run += v;
        }
    }
}

__global__ void scan_add_kernel(int M, int E) {
    int i = blockIdx.x * SCANB + threadIdx.x;
    if (i < M) g_rowptr[i] += g_bsum[blockIdx.x];
    if (i == 0) g_rowptr[M] = E;
}

__global__ void fill_kernel(const int* __restrict__ srcIdx,
                            const int* __restrict__ dstIdx, int E) {
    int e = blockIdx.x * blockDim.x + threadIdx.x;
    if (e >= E) return;
    int d = dstIdx[e];
    int pos = g_rowptr[d] + atomicAdd(&g_cursor[d], 1);
    g_col[pos] = srcIdx[e];
}

// ---------------- CSR aggregation (fp16 src, fp16 out, MLP=8) ----------------
template <int BN_FOLD>
__global__ void agg_csr_half_kernel(const __half* __restrict__ feat,
                                    __half* __restrict__ out, int M) {
    int node = blockIdx.x * 8 + (threadIdx.x >> 5);
    if (node >= M) return;
    int lane = threadIdx.x & 31;
    int e0 = __ldg(&g_rowptr[node]);
    int e1 = __ldg(&g_rowptr[node + 1]);
    const uint4* base = (const uint4*)feat;

    float acc[8];
    {
        uint4 v = base[(size_t)node * 32 + lane];
        const __half2* h2 = (const __half2*)&v;
#pragma unroll
        for (int p = 0; p < 4; p++) {
            float2 f = __half22float2(h2[p]);
            acc[p * 2] = f.x;
            acc[p * 2 + 1] = f.y;
        }
    }
    int e = e0;
    for (; e + 8 <= e1; e += 8) {
        int si[8];
#pragma unroll
        for (int j = 0; j < 8; j++) si[j] = __ldg(&g_col[e + j]);
        uint4 v[8];
#pragma unroll
        for (int j = 0; j < 8; j++) v[j] = base[(size_t)si[j] * 32 + lane];
#pragma unroll
        for (int j = 0; j < 8; j++) {
            const __half2* h2 = (const __half2*)&v[j];
#pragma unroll
            for (int p = 0; p < 4; p++) {
                float2 f = __half22float2(h2[p]);
                acc[p * 2] += f.x;
                acc[p * 2 + 1] += f.y;
            }
        }
    }
    for (; e + 4 <= e1; e += 4) {
        int s0 = __ldg(&g_col[e + 0]);
        int s1 = __ldg(&g_col[e + 1]);
        int s2 = __ldg(&g_col[e + 2]);
        int s3 = __ldg(&g_col[e + 3]);
        uint4 v0 = base[(size_t)s0 * 32 + lane];
        uint4 v1 = base[(size_t)s1 * 32 + lane];
        uint4 v2 = base[(size_t)s2 * 32 + lane];
        uint4 v3 = base[(size_t)s3 * 32 + lane];
        const __half2* a2 = (const __half2*)&v0;
        const __half2* b2 = (const __half2*)&v1;
        const __half2* c2 = (const __half2*)&v2;
        const __half2* d2 = (const __half2*)&v3;
#pragma unroll
        for (int p = 0; p < 4; p++) {
            float2 fa = __half22float2(a2[p]);
            float2 fb = __half22float2(b2[p]);
            float2 fc = __half22float2(c2[p]);
            float2 fd = __half22float2(d2[p]);
            acc[p * 2] += (fa.x + fb.x) + (fc.x + fd.x);
            acc[p * 2 + 1] += (fa.y + fb.y) + (fc.y + fd.y);
        }
    }
    for (; e < e1; e++) {
        int s = __ldg(&g_col[e]);
        uint4 v = base[(size_t)s * 32 + lane];
        const __half2* h2 = (const __half2*)&v;
#pragma unroll
        for (int p = 0; p < 4; p++) {
            float2 f = __half22float2(h2[p]);
            acc[p * 2] += f.x;
            acc[p * 2 + 1] += f.y;
        }
    }
    if (BN_FOLD) {
        float k = (float)(1 + (e1 - e0));
#pragma unroll
        for (int p = 0; p < 8; p++) {
            int c = lane * 8 + p;
            acc[p] = acc[p] * g_scale[c] + k * g_shift[c];
        }
    }
    uint4 o;
    __half2* o2 = (__half2*)&o;
#pragma unroll
    for (int p = 0; p < 4; p++)
        o2[p] = __floats2half2_rn(acc[p * 2], acc[p * 2 + 1]);
    ((uint4*)out)[(size_t)node * 32 + lane] = o;
}

// ---------------- common GEMM geometry ----------------
#define BK 32
#define AS 40    // As row stride (b16 elements)
#define BS 136   // Bs row stride (b16 elements)
#define NKT (D / BK)   // 8
#define AS_TILE (128 * AS)
#define BS_TILE (BK * BS)
// dynamic smem sizes (bytes)
#define SMEM_A_BYTES ((2 * AS_TILE + 4 * BS_TILE) * 2)               // gemm_a
#define SMEM_B_BYTES ((4 * AS_TILE + 4 * BS_TILE) * 2)               // gemm_b

// ---------------- GEMM-A: A fp16 exact, fp16 weights, 2-term ---------------
// Double-buffered smem, one __syncthreads per k-tile.
__global__ __launch_bounds__(512, 1) void gemm_a_kernel(
    const __half* __restrict__ A, const __half* __restrict__ Wh,
    const __half* __restrict__ Wl, const float* __restrict__ bias,
    __half* __restrict__ C, int M) {
    extern __shared__ __half sm_a[];
    __half* As = sm_a;                       // [2][AS_TILE]
    __half* Bs_h = As + 2 * AS_TILE;         // [2][BS_TILE]
    __half* Bs_l = Bs_h + 2 * BS_TILE;       // [2][BS_TILE]

    int bm = blockIdx.x * 128;
    int bn = blockIdx.y * 128;
    int tid = threadIdx.x;
    int lane = tid & 31;
    int wid = tid >> 5;
    int warp_m = wid >> 2;   // 0..3
    int warp_n = wid & 3;    // 0..3

    float acc[2][4][4];
#pragma unroll
    for (int i = 0; i < 2; i++)
#pragma unroll
        for (int j = 0; j < 4; j++)
#pragma unroll
            for (int r = 0; r < 4; r++) acc[i][j][r] = 0.f;

    int a_row = tid >> 2;
    int a_kh = (tid & 3) * 8;
    bool a_valid = (bm + a_row) < M;
    int b_row = tid >> 4;
    int b_c8 = (tid & 15) * 8;

    uint32_t as_base = (uint32_t)__cvta_generic_to_shared(As);
    uint32_t bs_h_base = (uint32_t)__cvta_generic_to_shared(Bs_h);
    uint32_t bs_l_base = (uint32_t)__cvta_generic_to_shared(Bs_l);

    uint4 a_pf, bh_pf, bl_pf;
    auto load_g = [&](int k0) {
        a_pf = a_valid ? *(const uint4*)(A + (size_t)(bm + a_row) * D + k0 + a_kh)
                       : make_uint4(0u, 0u, 0u, 0u);
        size_t goff = (size_t)(k0 + b_row) * D + bn + b_c8;
        bh_pf = *(const uint4*)(Wh + goff);
        bl_pf = *(const uint4*)(Wl + goff);
    };
    auto store_s = [&](int buf) {
        *(uint4*)&As[buf * AS_TILE + a_row * AS + a_kh] = a_pf;
        *(uint4*)&Bs_h[buf * BS_TILE + b_row * BS + b_c8] = bh_pf;
        *(uint4*)&Bs_l[buf * BS_TILE + b_row * BS + b_c8] = bl_pf;
    };

    load_g(0);
    store_s(0);
    if (NKT > 1) load_g(BK);
    __syncthreads();

    for (int kt = 0; kt < NKT; kt++) {
        int cur = kt & 1;
        if (kt + 1 < NKT) {
            store_s(cur ^ 1);                   // safe: buf cur^1 last read at kt-1
            if (kt + 2 < NKT) load_g((kt + 2) * BK);
        }
#pragma unroll
        for (int k16 = 0; k16 < BK; k16 += 16) {
            uint32_t ah[2][4];
            uint32_t bh[4][2];
            uint32_t bl[4][2];
#pragma unroll
            for (int mi = 0; mi < 2; mi++) {
                int row = warp_m * 32 + mi * 16 + (lane & 15);
                int col = k16 + ((lane >> 4) << 3);
                uint32_t ad = as_base + (uint32_t)(cur * AS_TILE + row * AS + col) * 2;
                asm volatile("ldmatrix.sync.aligned.m8n8.x4.shared.b16 {%0,%1,%2,%3}, [%4];"
                             : "=r"(ah[mi][0]), "=r"(ah[mi][1]), "=r"(ah[mi][2]), "=r"(ah[mi][3])
                             : "r"(ad));
            }
#pragma unroll
            for (int ni = 0; ni < 4; ni++) {
                int row = k16 + (lane & 15);
                int col = warp_n * 32 + ni * 8;
                uint32_t bd = bs_h_base + (uint32_t)(cur * BS_TILE + row * BS + col) * 2;
                asm volatile("ldmatrix.sync.aligned.m8n8.x2.trans.shared.b16 {%0,%1}, [%2];"
                             : "=r"(bh[ni][0]), "=r"(bh[ni][1]) : "r"(bd));
                uint32_t bd2 = bs_l_base + (uint32_t)(cur * BS_TILE + row * BS + col) * 2;
                asm volatile("ldmatrix.sync.aligned.m8n8.x2.trans.shared.b16 {%0,%1}, [%2];"
                             : "=r"(bl[ni][0]), "=r"(bl[ni][1]) : "r"(bd2));
            }
#pragma unroll
            for (int mi = 0; mi < 2; mi++) {
#pragma unroll
                for (int ni = 0; ni < 4; ni++) {
                    float* d = acc[mi][ni];
                    asm volatile(
                        "mma.sync.aligned.m16n8k16.row.col.f32.f16.f16.f32 "
                        "{%0,%1,%2,%3}, {%4,%5,%6,%7}, {%8,%9}, {%0,%1,%2,%3};"
                        : "+f"(d[0]), "+f"(d[1]), "+f"(d[2]), "+f"(d[3])
                        : "r"(ah[mi][0]), "r"(ah[mi][1]), "r"(ah[mi][2]), "r"(ah[mi][3]),
                          "r"(bh[ni][0]), "r"(bh[ni][1]));
                    asm volatile(
                        "mma.sync.aligned.m16n8k16.row.col.f32.f16.f16.f32 "
                        "{%0,%1,%2,%3}, {%4,%5,%6,%7}, {%8,%9}, {%0,%1,%2,%3};"
                        : "+f"(d[0]), "+f"(d[1]), "+f"(d[2]), "+f"(d[3])
                        : "r"(ah[mi][0]), "r"(ah[mi][1]), "r"(ah[mi][2]), "r"(ah[mi][3]),
                          "r"(bl[ni][0]), "r"(bl[ni][1]));
                }
            }
        }
        __syncthreads();
    }

    // epilogue: bias + fp16 store (no relu: feeds BN stats)
#pragma unroll
    for (int mi = 0; mi < 2; mi++) {
#pragma unroll
        for (int ni = 0; ni < 4; ni++) {
            int r0 = bm + warp_m * 32 + mi * 16 + (lane >> 2);
            int c0 = bn + warp_n * 32 + ni * 8 + (lane & 3) * 2;
            float b0 = bias[c0], b1 = bias[c0 + 1];
            float* d = acc[mi][ni];
            if (r0 < M)
                *(__half2*)&C[(size_t)r0 * D + c0] =
                    __floats2half2_rn(d[0] + b0, d[1] + b1);
            if (r0 + 8 < M)
                *(__half2*)&C[(size_t)(r0 + 8) * D + c0] =
                    __floats2half2_rn(d[2] + b0, d[3] + b1);
        }
    }
}

// ---------------- GEMM-B: A fp16 + BN/relu, bf16x3, double-buffered --------
template <int OUT_HALF>
__global__ __launch_bounds__(512, 1) void gemm_b_kernel(
    const __half* __restrict__ A, const __nv_bfloat16* __restrict__ Wh,
    const __nv_bfloat16* __restrict__ Wl, const float* __restrict__ bias,
    void* __restrict__ Cv, int M) {
    extern __shared__ __nv_bfloat16 sm_b[];
    __nv_bfloat16* As_h = sm_b;                  // [2][AS_TILE]
    __nv_bfloat16* As_l = As_h + 2 * AS_TILE;    // [2][AS_TILE]
    __nv_bfloat16* Bs_h = As_l + 2 * AS_TILE;    // [2][BS_TILE]
    __nv_bfloat16* Bs_l = Bs_h + 2 * BS_TILE;    // [2][BS_TILE]

    int bm = blockIdx.x * 128;
    int bn = blockIdx.y * 128;
    int tid = threadIdx.x;
    int lane = tid & 31;
    int wid = tid >> 5;
    int warp_m = wid >> 2;
    int warp_n = wid & 3;

    float acc[2][4][4];
#pragma unroll
    for (int i = 0; i < 2; i++)
#pragma unroll
        for (int j = 0; j < 4; j++)
#pragma unroll
            for (int r = 0; r < 4; r++) acc[i][j][r] = 0.f;

    int a_row = tid >> 2;
    int a_kh = (tid & 3) * 8;
    bool a_valid = (bm + a_row) < M;
    int b_row = tid >> 4;
    int b_c8 = (tid & 15) * 8;

    uint32_t as_h_base = (uint32_t)__cvta_generic_to_shared(As_h);
    uint32_t as_l_base = (uint32_t)__cvta_generic_to_shared(As_l);
    uint32_t bs_h_base = (uint32_t)__cvta_generic_to_shared(Bs_h);
    uint32_t bs_l_base = (uint32_t)__cvta_generic_to_shared(Bs_l);

    uint4 a_pf, bh_pf, bl_pf;
    auto load_g = [&](int k0) {
        a_pf = a_valid ? *(const uint4*)(A + (size_t)(bm + a_row) * D + k0 + a_kh)
                       : make_uint4(0u, 0u, 0u, 0u);
        size_t goff = (size_t)(k0 + b_row) * D + bn + b_c8;
        bh_pf = *(const uint4*)(Wh + goff);
        bl_pf = *(const uint4*)(Wl + goff);
    };
    auto store_s = [&](int buf, int k0) {
        const __half2* ah2 = (const __half2*)&a_pf;
        float f[8];
#pragma unroll
        for (int p = 0; p < 4; p++) {
            float2 t2 = __half22float2(ah2[p]);
            f[p * 2] = t2.x;
            f[p * 2 + 1] = t2.y;
        }
#pragma unroll
        for (int p = 0; p < 2; p++) {
            float4 s = ((const float4*)g_scale)[((k0 + a_kh) >> 2) + p];
            float4 sh = ((const float4*)g_shift)[((k0 + a_kh) >> 2) + p];
            f[p * 4 + 0] = fmaxf(f[p * 4 + 0] * s.x + sh.x, 0.f);
            f[p * 4 + 1] = fmaxf(f[p * 4 + 1] * s.y + sh.y, 0.f);
            f[p * 4 + 2] = fmaxf(f[p * 4 + 2] * s.z + sh.z, 0.f);
            f[p * 4 + 3] = fmaxf(f[p * 4 + 3] * s.w + sh.w, 0.f);
        }
        int off = buf * AS_TILE + a_row * AS + a_kh;
#pragma unroll
        for (int p = 0; p < 4; p++) {
            __nv_bfloat162 h2 = __floats2bfloat162_rn(f[p * 2], f[p * 2 + 1]);
            float2 fb = __bfloat1622float2(h2);
            __nv_bfloat162 l2 = __floats2bfloat162_rn(f[p * 2] - fb.x,
                                                      f[p * 2 + 1] - fb.y);
            *(__nv_bfloat162*)&As_h[off + p * 2] = h2;
            *(__nv_bfloat162*)&As_l[off + p * 2] = l2;
        }
        *(uint4*)&Bs_h[buf * BS_TILE + b_row * BS + b_c8] = bh_pf;
        *(uint4*)&Bs_l[buf * BS_TILE + b_row * BS + b_c8] = bl_pf;
    };

    load_g(0);
    store_s(0, 0);
    if (NKT > 1) load_g(BK);
    __syncthreads();

    for (int kt = 0; kt < NKT; kt++) {
        int cur = kt & 1;
        if (kt + 1 < NKT) {
            store_s(cur ^ 1, (kt + 1) * BK);
            if (kt + 2 < NKT) load_g((kt + 2) * BK);
        }
#pragma unroll
        for (int k16 = 0; k16 < BK; k16 += 16) {
            uint32_t ah[2][4];
            uint32_t al[2][4];
            uint32_t bh[4][2];
            uint32_t bl[4][2];
#pragma unroll
            for (int mi = 0; mi < 2; mi++) {
                int row = warp_m * 32 + mi * 16 + (lane & 15);
                int col = k16 + ((lane >> 4) << 3);
                uint32_t ad = as_h_base + (uint32_t)(cur * AS_TILE + row * AS + col) * 2;
                asm volatile("ldmatrix.sync.aligned.m8n8.x4.shared.b16 {%0,%1,%2,%3}, [%4];"
                             : "=r"(ah[mi][0]), "=r"(ah[mi][1]), "=r"(ah[mi][2]), "=r"(ah[mi][3])
                             : "r"(ad));
                uint32_t ad2 = as_l_base + (uint32_t)(cur * AS_TILE + row * AS + col) * 2;
                asm volatile("ldmatrix.sync.aligned.m8n8.x4.shared.b16 {%0,%1,%2,%3}, [%4];"
                             : "=r"(al[mi][0]), "=r"(al[mi][1]), "=r"(al[mi][2]), "=r"(al[mi][3])
                             : "r"(ad2));
            }
#pragma unroll
            for (int ni = 0; ni < 4; ni++) {
                int row = k16 + (lane & 15);
                int col = warp_n * 32 + ni * 8;
                uint32_t bd = bs_h_base + (uint32_t)(cur * BS_TILE + row * BS + col) * 2;
                asm volatile("ldmatrix.sync.aligned.m8n8.x2.trans.shared.b16 {%0,%1}, [%2];"
                             : "=r"(bh[ni][0]), "=r"(bh[ni][1]) : "r"(bd));
                uint32_t bd2 = bs_l_base + (uint32_t)(cur * BS_TILE + row * BS + col) * 2;
                asm volatile("ldmatrix.sync.aligned.m8n8.x2.trans.shared.b16 {%0,%1}, [%2];"
                             : "=r"(bl[ni][0]), "=r"(bl[ni][1]) : "r"(bd2));
            }
#pragma unroll
            for (int mi = 0; mi < 2; mi++) {
#pragma unroll
                for (int ni = 0; ni < 4; ni++) {
                    float* d = acc[mi][ni];
                    asm volatile(
                        "mma.sync.aligned.m16n8k16.row.col.f32.bf16.bf16.f32 "
                        "{%0,%1,%2,%3}, {%4,%5,%6,%7}, {%8,%9}, {%0,%1,%2,%3};"
                        : "+f"(d[0]), "+f"(d[1]), "+f"(d[2]), "+f"(d[3])
                        : "r"(ah[mi][0]), "r"(ah[mi][1]), "r"(ah[mi][2]), "r"(ah[mi][3]),
                          "r"(bh[ni][0]), "r"(bh[ni][1]));
                    asm volatile(
                        "mma.sync.aligned.m16n8k16.row.col.f32.bf16.bf16.f32 "
                        "{%0,%1,%2,%3}, {%4,%5,%6,%7}, {%8,%9}, {%0,%1,%2,%3};"
                        : "+f"(d[0]), "+f"(d[1]), "+f"(d[2]), "+f"(d[3])
                        : "r"(ah[mi][0]), "r"(ah[mi][1]), "r"(ah[mi][2]), "r"(ah[mi][3]),
                          "r"(bl[ni][0]), "r"(bl[ni][1]));
                    asm volatile(
                        "mma.sync.aligned.m16n8k16.row.col.f32.bf16.bf16.f32 "
                        "{%0,%1,%2,%3}, {%4,%5,%6,%7}, {%8,%9}, {%0,%1,%2,%3};"
                        : "+f"(d[0]), "+f"(d[1]), "+f"(d[2]), "+f"(d[3])
                        : "r"(al[mi][0]), "r"(al[mi][1]), "r"(al[mi][2]), "r"(al[mi][3]),
                          "r"(bh[ni][0]), "r"(bh[ni][1]));
                }
            }
        }
        __syncthreads();
    }

#pragma unroll
    for (int mi = 0; mi < 2; mi++) {
#pragma unroll
        for (int ni = 0; ni < 4; ni++) {
            int r0 = bm + warp_m * 32 + mi * 16 + (lane >> 2);
            int c0 = bn + warp_n * 32 + ni * 8 + (lane & 3) * 2;
            float b0 = bias[c0], b1 = bias[c0 + 1];
            float* d = acc[mi][ni];
            float2 v0 = make_float2(fmaxf(d[0] + b0, 0.f), fmaxf(d[1] + b1, 0.f));
            float2 v1 = make_float2(fmaxf(d[2] + b0, 0.f), fmaxf(d[3] + b1, 0.f));
            if (OUT_HALF) {
                __half* C = (__half*)Cv;
                if (r0 < M)
                    *(__half2*)&C[(size_t)r0 * D + c0] = __floats2half2_rn(v0.x, v0.y);
                if (r0 + 8 < M)
                    *(__half2*)&C[(size_t)(r0 + 8) * D + c0] = __floats2half2_rn(v1.x, v1.y);
            } else {
                float* C = (float*)Cv;
                if (r0 < M) *(float2*)&C[(size_t)r0 * D + c0] = v0;
                if (r0 + 8 < M) *(float2*)&C[(size_t)(r0 + 8) * D + c0] = v1;
            }
        }
    }
}

// ---------------- driver ----------------
extern "C" void kernel_launch(void* const* d_in, const int* in_sizes, int n_in,
                              void* d_out, int out_size) {
    const float* x = (const float*)d_in[0];
    const int* ei = (const int*)d_in[1];   // int32 (JAX x64 disabled)
    const float* g0 = (const float*)d_in[2];
    const float* b0 = (const float*)d_in[3];
    const float* W1a = (const float*)d_in[4];
    const float* b1a = (const float*)d_in[5];
    const float* g1 = (const float*)d_in[6];
    const float* bt1 = (const float*)d_in[7];
    const float* W1b = (const float*)d_in[8];
    const float* b1b = (const float*)d_in[9];
    const float* W2a = (const float*)d_in[10];
    const float* b2a = (const float*)d_in[11];
    const float* g2 = (const float*)d_in[12];
    const float* bt2 = (const float*)d_in[13];
    const float* W2b = (const float*)d_in[14];
    const float* b2b = (const float*)d_in[15];
    float* out = (float*)d_out;

    int M = in_sizes[0] / D;
    int E = in_sizes[1] / 2;
    const int* srcI = ei;
    const int* dstI = ei + E;

    __half *t, *u, *xh, *hh;
    cudaGetSymbolAddress((void**)&t, g_t);
    cudaGetSymbolAddress((void**)&u, g_u);
    cudaGetSymbolAddress((void**)&xh, g_xh);
    cudaGetSymbolAddress((void**)&hh, g_hh);
    __nv_bfloat16 *wh, *wl;
    cudaGetSymbolAddress((void**)&wh, g_wh);
    cudaGetSymbolAddress((void**)&wl, g_wl);
    __half *fh, *fl;
    cudaGetSymbolAddress((void**)&fh, g_fh);
    cudaGetSymbolAddress((void**)&fl, g_fl);
    __nv_bfloat16* Wh[4] = {wh, wh + D * D, wh + 2 * D * D, wh + 3 * D * D};
    __nv_bfloat16* Wl[4] = {wl, wl + D * D, wl + 2 * D * D, wl + 3 * D * D};
    __half* Fh[4] = {fh, fh + D * D, fh + 2 * D * D, fh + 3 * D * D};
    __half* Fl[4] = {fl, fl + D * D, fl + 2 * D * D, fl + 3 * D * D};

    static int attr_done = 0;
    if (!attr_done) {
        cudaFuncSetAttribute(gemm_a_kernel,
                             cudaFuncAttributeMaxDynamicSharedMemorySize, SMEM_A_BYTES);
        cudaFuncSetAttribute(gemm_b_kernel<1>,
                             cudaFuncAttributeMaxDynamicSharedMemorySize, SMEM_B_BYTES);
        cudaFuncSetAttribute(gemm_b_kernel<0>,
                             cudaFuncAttributeMaxDynamicSharedMemorySize, SMEM_B_BYTES);
        attr_done = 1;
    }

    dim3 gemmGrid((M + 127) / 128, 2);
    int aggGrid = (M + 7) / 8;
    int nb = (M + SCANB - 1) / SCANB;

    // ---- pre-convert weights (one launch for all 4, both formats) ----
    convert_w_kernel<<<dim3((D * D / 2) / 256, 4), 256>>>(W1a, W1b, W2a, W2b);

    // ---- build CSR once (reused by both convs) ----
    zero_deg_kernel<<<(M + 255) / 256, 256>>>(M);
    hist_kernel<<<(E + 255) / 256, 256>>>(dstI, E);
    scan_block_kernel<<<nb, SCANB>>>(M);
    scan_bsum_kernel<<<1, 32>>>(nb);
    scan_add_kernel<<<nb, SCANB>>>(M, E);
    fill_kernel<<<(E + 255) / 256, 256>>>(srcI, dstI, E);

    // ---- BN0 stats on x (+ fp16 copy); agg with BN folded ----
    zero_stats_kernel<<<1, 256>>>();
    stats_kernel<1><<<512, 256>>>(x, xh, M);
    finalize_stats_kernel<<<1, 256>>>(g0, b0, M);
    agg_csr_half_kernel<1><<<aggGrid, 256>>>(xh, t, M);                 // t = BN0-agg(x)

    // ---- conv1 ----
    gemm_a_kernel<<<gemmGrid, 512, SMEM_A_BYTES>>>(t, Fh[0], Fl[0], b1a, u, M);
    zero_stats_kernel<<<1, 256>>>();
    stats_half_kernel<<<512, 256>>>(u, M);
    finalize_stats_kernel<<<1, 256>>>(g1, bt1, M);
    gemm_b_kernel<1><<<gemmGrid, 512, SMEM_B_BYTES>>>(u, Wh[1], Wl[1], b1b, hh, M);

    // ---- conv2 ----
    agg_csr_half_kernel<0><<<aggGrid, 256>>>(hh, t, M);                 // t = h + Σh
    gemm_a_kernel<<<gemmGrid, 512, SMEM_A_BYTES>>>(t, Fh[2], Fl[2], b2a, u, M);
    zero_stats_kernel<<<1, 256>>>();
    stats_half_kernel<<<512, 256>>>(u, M);
    finalize_stats_kernel<<<1, 256>>>(g2, bt2, M);
    gemm_b_kernel<0><<<gemmGrid, 512, SMEM_B_BYTES>>>(u, Wh[3], Wl[3], b2b, out, M);
}